// round 3
// baseline (speedup 1.0000x reference)
#include <cuda_runtime.h>
#include <float.h>

// features: [B=8, X=128, Y=128, C=128] f32   (C contiguous)
// rois:     [B, N=128, 4] i32  (minX, minY, maxX, maxY)
// out:      [B, N, 7, 7, C] f32
// out[b,n,h,w,c] = max over x in xbin(w), y in ybin(h) of features[b,x,y,c]

#define PH 7
#define PW 7
#define B_ 8
#define N_ 128
#define XDIM 128
#define YDIM 128
#define CDIM 128
#define C4   (CDIM / 4)          // 32 float4 per pixel
#define WPB  8                    // warps per block
#define TOTAL_BINS (B_ * N_ * PH * PW)   // 50176

__device__ __forceinline__ float4 f4max(float4 a, float4 b) {
    return make_float4(fmaxf(a.x, b.x), fmaxf(a.y, b.y),
                       fmaxf(a.z, b.z), fmaxf(a.w, b.w));
}

__global__ __launch_bounds__(WPB * 32, 6)
void roi_maxpool_kernel(const float4* __restrict__ features,
                        const int4*   __restrict__ rois,
                        float4*       __restrict__ out)
{
    // one warp per output bin (b, n, h, w)
    int gw   = blockIdx.x * WPB + (threadIdx.x >> 5);
    int lane = threadIdx.x & 31;

    int w  = gw % PW;
    int t  = gw / PW;
    int h  = t % PH;
    t      = t / PH;          // t = b*N_ + n
    int b  = t >> 7;          // /N_

    const int4 r = rois[t];
    int minX = r.x, minY = r.y, maxX = r.z, maxY = r.w;

    int dx = (maxX - minX) / PW;
    int dy = (maxY - minY) / PH;

    int y0 = minY + h * dy;
    int ny = (h == PH - 1) ? (maxY - y0) : dy;
    int x0 = minX + w * dx;
    int x1 = (w == PW - 1) ? maxX : (x0 + dx);

    const float4 NEG = make_float4(-FLT_MAX, -FLT_MAX, -FLT_MAX, -FLT_MAX);
    float4 m0 = NEG;
    float4 m1 = NEG;

    // 32-bit indexing: max index = 8*128*128*32 = 4.19M  < 2^31
    const int col_stride = YDIM * C4;   // +1 in x
    const float4* base = features + (b * XDIM * YDIM * C4) + y0 * C4 + lane;

    int x = x0;
    for (; x + 2 <= x1; x += 2) {
        const float4* p0 = base + x * col_stride;
        const float4* p1 = p0 + col_stride;
        int y = 0;
        for (; y + 2 <= ny; y += 2) {
            float4 a0 = p0[(y + 0) * C4];
            float4 a1 = p0[(y + 1) * C4];
            float4 b0 = p1[(y + 0) * C4];
            float4 b1 = p1[(y + 1) * C4];
            m0 = f4max(m0, f4max(a0, a1));
            m1 = f4max(m1, f4max(b0, b1));
        }
        if (y < ny) {
            m0 = f4max(m0, p0[y * C4]);
            m1 = f4max(m1, p1[y * C4]);
        }
    }
    if (x < x1) {
        const float4* p0 = base + x * col_stride;
        int y = 0;
        for (; y + 2 <= ny; y += 2) {
            float4 a0 = p0[(y + 0) * C4];
            float4 a1 = p0[(y + 1) * C4];
            m0 = f4max(m0, f4max(a0, a1));
        }
        if (y < ny) {
            m0 = f4max(m0, p0[y * C4]);
        }
    }

    float4 m = f4max(m0, m1);
    out[gw * C4 + lane] = m;   // gw enumerates (b,n,h,w) in output order
}

extern "C" void kernel_launch(void* const* d_in, const int* in_sizes, int n_in,
                              void* d_out, int out_size)
{
    const float4* features = (const float4*)d_in[0];
    const int4*   rois     = (const int4*)d_in[1];
    float4*       out      = (float4*)d_out;

    dim3 grid(TOTAL_BINS / WPB);     // 6272, exact
    dim3 block(WPB * 32);            // 256
    roi_maxpool_kernel<<<grid, block>>>(features, rois, out);
}

// round 4
// speedup vs baseline: 1.1291x; 1.1291x over previous
#include <cuda_runtime.h>
#include <float.h>

// features: [B=8, X=128, Y=128, C=128] f32   (C contiguous)
// rois:     [B, N=128, 4] i32  (minX, minY, maxX, maxY)
// out:      [B, N, 7, 7, C] f32
// out[b,n,h,w,c] = max over x in xbin(w), y in ybin(h) of features[b,x,y,c]

#define PH 7
#define PW 7
#define B_ 8
#define N_ 128
#define XDIM 128
#define YDIM 128
#define CDIM 128
#define C4   (CDIM / 4)                  // 32 float4 per pixel
#define WPB  8                           // warps per block
#define TOTAL_BINS (B_ * N_ * PH * PW)   // 50176

__device__ __forceinline__ float4 f4max(float4 a, float4 b) {
    return make_float4(fmaxf(a.x, b.x), fmaxf(a.y, b.y),
                       fmaxf(a.z, b.z), fmaxf(a.w, b.w));
}

__global__ __launch_bounds__(WPB * 32, 5)
void roi_maxpool_kernel(const float4* __restrict__ features,
                        const int4*   __restrict__ rois,
                        float4*       __restrict__ out)
{
    // one warp per output bin (b, n, h, w)
    int gw   = blockIdx.x * WPB + (threadIdx.x >> 5);
    int lane = threadIdx.x & 31;

    int w  = gw % PW;
    int t  = gw / PW;
    int h  = t % PH;
    t      = t / PH;          // t = b*N_ + n
    int b  = t >> 7;          // /N_

    const int4 r = rois[t];
    int minX = r.x, minY = r.y, maxX = r.z, maxY = r.w;

    int dx = (maxX - minX) / PW;
    int dy = (maxY - minY) / PH;

    int y0 = minY + h * dy;
    int ny = (h == PH - 1) ? (maxY - y0) : dy;
    int x0 = minX + w * dx;
    int x1 = (w == PW - 1) ? maxX : (x0 + dx);

    const float4 NEG = make_float4(-FLT_MAX, -FLT_MAX, -FLT_MAX, -FLT_MAX);
    float4 m0 = NEG;
    float4 m1 = NEG;

    // 32-bit indexing: max index = 8*128*128*32 = 4.19M < 2^31
    const int col_stride = YDIM * C4;   // +1 in x
    const float4* base = features + (b * XDIM * YDIM * C4) + y0 * C4 + lane;

    int x = x0;
    // two x-columns at a time, four y-rows at a time: 8 independent LDG.128
    for (; x + 2 <= x1; x += 2) {
        const float4* p0 = base + x * col_stride;
        const float4* p1 = p0 + col_stride;
        int y = 0;
        for (; y + 4 <= ny; y += 4) {
            float4 a0 = p0[(y + 0) * C4];
            float4 a1 = p0[(y + 1) * C4];
            float4 a2 = p0[(y + 2) * C4];
            float4 a3 = p0[(y + 3) * C4];
            float4 b0 = p1[(y + 0) * C4];
            float4 b1 = p1[(y + 1) * C4];
            float4 b2 = p1[(y + 2) * C4];
            float4 b3 = p1[(y + 3) * C4];
            m0 = f4max(m0, f4max(f4max(a0, a1), f4max(a2, a3)));
            m1 = f4max(m1, f4max(f4max(b0, b1), f4max(b2, b3)));
        }
        for (; y < ny; ++y) {
            m0 = f4max(m0, p0[y * C4]);
            m1 = f4max(m1, p1[y * C4]);
        }
    }
    // remainder single x-column
    if (x < x1) {
        const float4* p0 = base + x * col_stride;
        int y = 0;
        for (; y + 4 <= ny; y += 4) {
            float4 a0 = p0[(y + 0) * C4];
            float4 a1 = p0[(y + 1) * C4];
            float4 a2 = p0[(y + 2) * C4];
            float4 a3 = p0[(y + 3) * C4];
            m0 = f4max(m0, f4max(f4max(a0, a1), f4max(a2, a3)));
        }
        for (; y < ny; ++y) {
            m0 = f4max(m0, p0[y * C4]);
        }
    }

    float4 m = f4max(m0, m1);
    out[gw * C4 + lane] = m;   // gw enumerates (b,n,h,w) in output order
}

extern "C" void kernel_launch(void* const* d_in, const int* in_sizes, int n_in,
                              void* d_out, int out_size)
{
    const float4* features = (const float4*)d_in[0];
    const int4*   rois     = (const int4*)d_in[1];
    float4*       out      = (float4*)d_out;

    dim3 grid(TOTAL_BINS / WPB);     // 6272, exact
    dim3 block(WPB * 32);            // 256
    roi_maxpool_kernel<<<grid, block>>>(features, rois, out);
}

// round 5
// speedup vs baseline: 1.2099x; 1.0716x over previous
#include <cuda_runtime.h>
#include <float.h>

// features: [B=8, X=128, Y=128, C=128] f32   (C contiguous)
// rois:     [B, N=128, 4] i32  (minX, minY, maxX, maxY)
// out:      [B, N, 7, 7, C] f32
// out[b,n,h,w,c] = max over x in xbin(w), y in ybin(h) of features[b,x,y,c]
//
// Guarantees from the generator: ROI side >= 2*pool, so dx,dy >= 2 and
// every bin is at least 2x2. Max is idempotent -> cover each bin with 2x2
// tiles whose last tile is shifted to end at the bin edge (overlap OK).

#define PH 7
#define PW 7
#define B_ 8
#define N_ 128
#define XDIM 128
#define YDIM 128
#define CDIM 128
#define C4   (CDIM / 4)          // 32 float4 per pixel
#define COLS (YDIM * C4)         // float4 stride for +1 in x (4096)

__device__ __forceinline__ float4 f4max(float4 a, float4 b) {
    return make_float4(fmaxf(a.x, b.x), fmaxf(a.y, b.y),
                       fmaxf(a.z, b.z), fmaxf(a.w, b.w));
}

__global__ __launch_bounds__(PW * 32)
void roi_maxpool_kernel(const float4* __restrict__ features,
                        const int4*   __restrict__ rois,
                        float4*       __restrict__ out)
{
    // one block per (b, n, h); one warp per w-bin
    int bid  = blockIdx.x;
    int h    = bid % PH;
    int t    = bid / PH;          // t = b*N_ + n
    int b    = t >> 7;            // / N_
    int w    = threadIdx.x >> 5;
    int lane = threadIdx.x & 31;

    const int4 r = rois[t];
    int minX = r.x, minY = r.y, maxX = r.z, maxY = r.w;

    int dx = (maxX - minX) / PW;
    int dy = (maxY - minY) / PH;

    int y0 = minY + h * dy;
    int ny = (h == PH - 1) ? (maxY - y0) : dy;   // >= 2
    int x0 = minX + w * dx;
    int nx = (w == PW - 1) ? (maxX - x0) : dx;   // >= 2

    int nxp = (nx + 1) >> 1;   // number of 2-wide x tiles (last one shifted)
    int nyp = (ny + 1) >> 1;   // number of 2-tall y tiles (last one shifted)

    const float4 NEG = make_float4(-FLT_MAX, -FLT_MAX, -FLT_MAX, -FLT_MAX);
    float4 m0 = NEG, m1 = NEG, m2 = NEG, m3 = NEG;

    // base for [b, x0-rel, y0, lane]; 32-bit indexing (max 4.19M < 2^31)
    const float4* base = features + (b * XDIM * COLS) + x0 * COLS + y0 * C4 + lane;
    int xlast = (nx - 2) * COLS;   // offset of last (shifted) x tile
    int ylast = (ny - 2) * C4;     // offset of last (shifted) y tile

    for (int j = 0; j < nxp; ++j) {
        int xoff = min(j * 2 * COLS, xlast);
        const float4* pc = base + xoff;
        #pragma unroll 2
        for (int i = 0; i < nyp; ++i) {
            int yoff = min(i * 2 * C4, ylast);
            const float4* p = pc + yoff;
            float4 a0 = p[0];
            float4 a1 = p[C4];
            float4 b0 = p[COLS];
            float4 b1 = p[COLS + C4];
            m0 = f4max(m0, a0);
            m1 = f4max(m1, a1);
            m2 = f4max(m2, b0);
            m3 = f4max(m3, b1);
        }
    }

    float4 m = f4max(f4max(m0, m1), f4max(m2, m3));

    // output index: ((t*PH + h)*PW + w)*C4 + lane ; note bid = t*PH + h
    out[(bid * PW + w) * C4 + lane] = m;
}

extern "C" void kernel_launch(void* const* d_in, const int* in_sizes, int n_in,
                              void* d_out, int out_size)
{
    const float4* features = (const float4*)d_in[0];
    const int4*   rois     = (const int4*)d_in[1];
    float4*       out      = (float4*)d_out;

    dim3 grid(B_ * N_ * PH);     // 7168
    dim3 block(PW * 32);         // 224
    roi_maxpool_kernel<<<grid, block>>>(features, rois, out);
}